// round 10
// baseline (speedup 1.0000x reference)
#include <cuda_runtime.h>

// B=8, MSP=2048, D=512, A=64, NB=5
// Exact contraction reordering:
//   Wc[n,d]   = W_fl[n,d] + W_fl[n,512+d]
//   S[n]      = sum_d Wc[n,d]
//   t[b,s,n]  = sum_d e[b,s,d] * Wc[n,d]
//   out[b,a,n]= sum_s W_ll[a,s] * t[b,s,n] + b_ll[a]*S[n] + b_fl[n]
//   final[b,i,j,n] = out[b,i,n]
//
// SINGLE kernel, 296 blocks x 192 threads (exactly 2 blocks/SM).
// 37 blocks per b; block owns a ~55-row s-slice. Each warp: ~9 rows with a
// TRUE depth-2 load pipeline (3 register slots: compute row i while rows
// i+1 and i+2 are in flight). Per row: t via FFMA2 + butterfly, fold into
// per-lane register accumulators (a=lane, lane+32) using W_ll from a
// conflict-free transposed smem tile. Block epilogue: smem-combine +
// 320 atomicAdds. Last-of-37 block per b (ticket) applies biases, writes
// the b's 80KB output slab, and resets state for the next graph replay.

#define DVAL   512
#define NB     5
#define AVAL   64
#define BVAL   8
#define MSP    2048
#define GRID   296
#define TPB    192
#define KPB    37             // blocks per b
#define WPB    6              // warps per block
#define MAXNS  56             // max rows per block (ceil(2048/37))

__device__ float g_out2[BVAL * AVAL * NB];   // 2560 floats, zero at launch entry
__device__ int   g_tick[BVAL];               // per-b completion tickets

__device__ __forceinline__ unsigned long long fma2(unsigned long long a,
                                                   unsigned long long b,
                                                   unsigned long long c) {
    unsigned long long d;
    asm("fma.rn.f32x2 %0, %1, %2, %3;" : "=l"(d) : "l"(a), "l"(b), "l"(c));
    return d;
}
__device__ __forceinline__ float unpack_add(unsigned long long v) {
    float lo, hi;
    asm("mov.b64 {%0, %1}, %2;" : "=f"(lo), "=f"(hi) : "l"(v));
    return lo + hi;
}

__global__ __launch_bounds__(TPB, 2) void fused_kernel(const float* __restrict__ e,
                                                       const float* __restrict__ W_fl,
                                                       const float* __restrict__ W_ll,
                                                       const float* __restrict__ b_ll,
                                                       const float* __restrict__ b_fl,
                                                       float* __restrict__ out) {
    __shared__ __align__(16) float wcs[NB * DVAL];       // 10 KB
    __shared__ float wllT[MAXNS * 65];                   // 14.2 KB, pad-65
    __shared__ float sacc[WPB][AVAL * NB];               // 7.5 KB
    __shared__ float sS[NB];
    __shared__ float vfin[AVAL * NB];
    __shared__ __align__(16) float pat[AVAL * 20];       // 5 KB (finisher)
    __shared__ int   my_ticket;

    const int tid  = threadIdx.x;
    const int lane = tid & 31;
    const int warp = tid >> 5;
    const int b    = blockIdx.x / KPB;
    const int k    = blockIdx.x - b * KPB;
    const int s0B  = (k * MSP) / KPB;
    const int s1B  = ((k + 1) * MSP) / KPB;
    const int nS   = s1B - s0B;                          // 55 or 56

    // ---- stage Wc ----
    for (int i = tid; i < NB * DVAL; i += TPB) {
        int n = i / DVAL, d = i - n * DVAL;
        wcs[i] = W_fl[n * 1024 + d] + W_fl[n * 1024 + 512 + d];
    }
    // ---- stage W_ll transposed: wllT[sl][a]; sl fastest -> coalesced LDG ----
    for (int i = tid; i < AVAL * nS; i += TPB) {
        int a = i / nS, sl = i - a * nS;
        wllT[sl * 65 + a] = W_ll[(size_t)a * MSP + s0B + sl];
    }
    __syncthreads();

    // ---- S (warp 0 of every block; used only by finisher) ----
    if (warp == 0) {
        #pragma unroll
        for (int n = 0; n < NB; n++) {
            float s = 0.f;
            for (int d = lane; d < DVAL; d += 32) s += wcs[n * DVAL + d];
            #pragma unroll
            for (int off = 16; off > 0; off >>= 1)
                s += __shfl_xor_sync(0xFFFFFFFFu, s, off);
            if (lane == 0) sS[n] = s;
        }
    }

    // ---- Wc r=0..2 in registers (60 regs); r=3 re-read from smem per row ----
    ulonglong2 wc2[3][NB];
    #pragma unroll
    for (int r = 0; r < 3; r++)
        #pragma unroll
        for (int n = 0; n < NB; n++)
            wc2[r][n] = *(const ulonglong2*)&wcs[n * DVAL + r * 128 + lane * 4];

    // ---- warp row range within the block slice ----
    const int w0 = (warp * nS) / WPB;
    const int w1 = ((warp + 1) * nS) / WPB;
    const float* ebase = e + ((size_t)b * MSP + s0B) * DVAL;

    float accA0[NB], accA1[NB];
    #pragma unroll
    for (int n = 0; n < NB; n++) { accA0[n] = 0.f; accA1[n] = 0.f; }

    // ---- depth-2 pipeline: 3 register slots ----
    ulonglong2 ev[3][4];
    #define LOADROW(I, SLOT)                                                   \
        if ((I) < w1) {                                                        \
            const ulonglong2* er_ = (const ulonglong2*)(ebase + (size_t)(I) * DVAL); \
            _Pragma("unroll")                                                  \
            for (int r_ = 0; r_ < 4; r_++) ev[SLOT][r_] = er_[r_ * 32 + lane]; \
        }

    LOADROW(w0,     w0 % 3);
    LOADROW(w0 + 1, (w0 + 1) % 3);

    for (int i = w0; i < w1; i++) {
        LOADROW(i + 2, (i + 2) % 3);          // keep 2 rows in flight
        const int slot = i % 3;

        // wc r=3 from smem (conflict-free: 16B/lane stride)
        ulonglong2 wc3[NB];
        #pragma unroll
        for (int n = 0; n < NB; n++)
            wc3[n] = *(const ulonglong2*)&wcs[n * DVAL + 384 + lane * 4];

        unsigned long long acc2[NB];
        #pragma unroll
        for (int n = 0; n < NB; n++) acc2[n] = 0ull;
        #pragma unroll
        for (int r = 0; r < 3; r++) {
            #pragma unroll
            for (int n = 0; n < NB; n++) {
                acc2[n] = fma2(ev[slot][r].x, wc2[r][n].x, acc2[n]);
                acc2[n] = fma2(ev[slot][r].y, wc2[r][n].y, acc2[n]);
            }
        }
        #pragma unroll
        for (int n = 0; n < NB; n++) {
            acc2[n] = fma2(ev[slot][3].x, wc3[n].x, acc2[n]);
            acc2[n] = fma2(ev[slot][3].y, wc3[n].y, acc2[n]);
        }

        float t[NB];
        #pragma unroll
        for (int n = 0; n < NB; n++) t[n] = unpack_add(acc2[n]);
        #pragma unroll
        for (int n = 0; n < NB; n++) {
            #pragma unroll
            for (int off = 16; off > 0; off >>= 1)
                t[n] += __shfl_xor_sync(0xFFFFFFFFu, t[n], off);
        }

        const float wl0 = wllT[i * 65 + lane];
        const float wl1 = wllT[i * 65 + 32 + lane];
        #pragma unroll
        for (int n = 0; n < NB; n++) {
            accA0[n] += wl0 * t[n];
            accA1[n] += wl1 * t[n];
        }
    }
    #undef LOADROW

    // ---- epilogue: combine warps, one atomicAdd per element per block ----
    {
        float* sp = sacc[warp];
        #pragma unroll
        for (int n = 0; n < NB; n++) {
            sp[lane * NB + n]        = accA0[n];
            sp[(lane + 32) * NB + n] = accA1[n];
        }
    }
    __syncthreads();
    for (int idx = tid; idx < AVAL * NB; idx += TPB) {
        float sum = 0.f;
        #pragma unroll
        for (int w = 0; w < WPB; w++) sum += sacc[w][idx];
        atomicAdd(&g_out2[b * (AVAL * NB) + idx], sum);
    }

    // ---- ticket: last of the 37 blocks of this b finalizes ----
    __threadfence();
    __syncthreads();
    if (tid == 0) my_ticket = atomicAdd(&g_tick[b], 1);
    __syncthreads();
    if (my_ticket != KPB - 1) return;

    {
        volatile float* gp = &g_out2[b * (AVAL * NB)];
        for (int idx = tid; idx < AVAL * NB; idx += TPB) {
            const int a = idx / NB, n = idx - a * NB;
            float x = gp[idx];
            vfin[idx] = x + b_ll[a] * sS[n] + b_fl[n];
            gp[idx] = 0.f;                         // reset for next replay
        }
        if (tid == 0) g_tick[b] = 0;               // reset ticket
    }
    __syncthreads();

    for (int i = tid; i < AVAL * 20; i += TPB)
        pat[i] = vfin[(i / 20) * NB + (i % NB)];
    __syncthreads();

    // 64 i x 80 float4 (20-float pattern repeats 4x per 80)
    float4* ob = (float4*)(out + (size_t)b * AVAL * AVAL * NB);
    const float4* p4 = (const float4*)pat;
    for (int g = tid; g < AVAL * 80; g += TPB) {
        const int i = g / 80;
        ob[g] = p4[i * 5 + (g % 80) % 5];
    }
}

// ---------------------------------------------------------------------------
extern "C" void kernel_launch(void* const* d_in, const int* in_sizes, int n_in,
                              void* d_out, int out_size) {
    const float* e    = (const float*)d_in[0];
    const float* W_ll = (const float*)d_in[1];
    const float* b_ll = (const float*)d_in[2];
    const float* W_fl = (const float*)d_in[3];
    const float* b_fl = (const float*)d_in[4];
    float* out = (float*)d_out;

    fused_kernel<<<GRID, TPB>>>(e, W_fl, W_ll, b_ll, b_fl, out);
}

// round 11
// speedup vs baseline: 1.0941x; 1.0941x over previous
#include <cuda_runtime.h>

// B=8, MSP=2048, D=512, A=64, NB=5
// Exact contraction reordering:
//   Wc[n,d]   = W_fl[n,d] + W_fl[n,512+d]
//   S[n]      = sum_d Wc[n,d]
//   t[b,s,n]  = sum_d e[b,s,d] * Wc[n,d]     (stored transposed g_tT[n][row])
//   out[b,a,n]= sum_s W_ll[a,s] * t[b,s,n] + b_ll[a]*S[n] + b_fl[n]
//   final[b,i,j,n] = out[b,i,n]
//
// SINGLE launch: 296 blocks x 256 threads (exactly 2 blocks/SM, all
// resident -> software grid barriers are deadlock-free).
//   Phase 1: R5's proven t loop (float4, static depth-1 prefetch, Wc in
//            80 regs), t stored transposed.
//   barrier
//   Phase 2: R5's out warp-tasks (b, a, 256-s chunk) -> atomicAdd partials.
//   barrier
//   Phase 3: all threads write the 640 KB broadcast output.
//   Last-finisher ticket resets g_out2 + counters for the next graph replay.

#define NROWS  16384
#define DVAL   512
#define NB     5
#define AVAL   64
#define BVAL   8
#define MSP    2048
#define GRID   296
#define TPB    256
#define NWARP  (GRID * 8)      // 2368

__device__ int   g_bar1, g_bar2, g_fin;
__device__ float g_S[NB];
__device__ float g_tT[NB * NROWS];           // 320 KB, L2-resident
__device__ float g_out2[BVAL * AVAL * NB];   // 2560 floats, zero at launch entry

__device__ __forceinline__ void grid_barrier(int* ctr) {
    __threadfence();
    __syncthreads();
    if (threadIdx.x == 0) {
        atomicAdd(ctr, 1);
        while (*(volatile int*)ctr < GRID) { }
    }
    __syncthreads();
}

__global__ __launch_bounds__(TPB, 2) void fused_kernel(const float* __restrict__ e,
                                                       const float* __restrict__ W_fl,
                                                       const float* __restrict__ W_ll,
                                                       const float* __restrict__ b_ll,
                                                       const float* __restrict__ b_fl,
                                                       float* __restrict__ out) {
    __shared__ __align__(16) float wcs[NB * DVAL];   // 10 KB
    const int tid  = threadIdx.x;
    const int lane = tid & 31;
    const int warp = tid >> 5;

    // ================= Phase 1: t (R5 loop, transposed store) ==============
    for (int i = tid; i < NB * DVAL; i += TPB) {
        int n = i / DVAL, d = i - n * DVAL;
        wcs[i] = W_fl[n * 1024 + d] + W_fl[n * 1024 + 512 + d];
    }
    __syncthreads();

    if (blockIdx.x == 0 && warp == 0) {
        #pragma unroll
        for (int n = 0; n < NB; n++) {
            float s = 0.f;
            for (int d = lane; d < DVAL; d += 32) s += wcs[n * DVAL + d];
            #pragma unroll
            for (int off = 16; off > 0; off >>= 1)
                s += __shfl_xor_sync(0xFFFFFFFFu, s, off);
            if (lane == 0) g_S[n] = s;
        }
    }

    // Per-lane Wc registers: lane owns d = r*128 + lane*4 .. +3
    float4 wc[4][NB];
    #pragma unroll
    for (int r = 0; r < 4; r++)
        #pragma unroll
        for (int n = 0; n < NB; n++)
            wc[r][n] = *(const float4*)&wcs[n * DVAL + r * 128 + lane * 4];

    const int gw = blockIdx.x * 8 + warp;

    int row = gw;
    float4 ev[4];
    if (row < NROWS) {
        const float4* er = (const float4*)(e + (size_t)row * DVAL);
        #pragma unroll
        for (int r = 0; r < 4; r++) ev[r] = er[r * 32 + lane];
    }
    while (row < NROWS) {
        const int nxt = row + NWARP;
        float4 ev2[4];
        if (nxt < NROWS) {
            const float4* er2 = (const float4*)(e + (size_t)nxt * DVAL);
            #pragma unroll
            for (int r = 0; r < 4; r++) ev2[r] = er2[r * 32 + lane];
        }

        float acc[NB];
        #pragma unroll
        for (int n = 0; n < NB; n++) acc[n] = 0.f;
        #pragma unroll
        for (int r = 0; r < 4; r++) {
            #pragma unroll
            for (int n = 0; n < NB; n++) {
                acc[n] += ev[r].x * wc[r][n].x;
                acc[n] += ev[r].y * wc[r][n].y;
                acc[n] += ev[r].z * wc[r][n].z;
                acc[n] += ev[r].w * wc[r][n].w;
            }
        }
        #pragma unroll
        for (int n = 0; n < NB; n++) {
            #pragma unroll
            for (int off = 16; off > 0; off >>= 1)
                acc[n] += __shfl_xor_sync(0xFFFFFFFFu, acc[n], off);
        }
        if (lane < NB) {
            float v = (lane == 0) ? acc[0] : (lane == 1) ? acc[1] :
                      (lane == 2) ? acc[2] : (lane == 3) ? acc[3] : acc[4];
            g_tT[lane * NROWS + row] = v;     // transposed for phase-2 coalescing
        }
        #pragma unroll
        for (int r = 0; r < 4; r++) ev[r] = ev2[r];
        row = nxt;
    }

    grid_barrier(&g_bar1);

    // ================= Phase 2: out partials =============================
    // 4096 warp-tasks = (b:8) x (a:64) x (s-chunk:8 of 256).
    for (int task = gw; task < 4096; task += NWARP) {
        const int ch = task & 7;
        const int a  = (task >> 3) & 63;
        const int b  = task >> 9;
        const int sb = ch * 256;

        const float* wrow = W_ll + (size_t)a * MSP + sb;
        float wv[8];
        #pragma unroll
        for (int k = 0; k < 8; k++) wv[k] = wrow[lane + 32 * k];

        float a0 = 0.f, a1 = 0.f, a2 = 0.f, a3 = 0.f, a4 = 0.f;
        #pragma unroll
        for (int n = 0; n < 1; n++) { }   // (keep structure flat below)
        {
            const float* tp0 = g_tT + 0 * NROWS + (size_t)b * MSP + sb;
            const float* tp1 = g_tT + 1 * NROWS + (size_t)b * MSP + sb;
            const float* tp2 = g_tT + 2 * NROWS + (size_t)b * MSP + sb;
            const float* tp3 = g_tT + 3 * NROWS + (size_t)b * MSP + sb;
            const float* tp4 = g_tT + 4 * NROWS + (size_t)b * MSP + sb;
            #pragma unroll
            for (int k = 0; k < 8; k++) {
                const int s = lane + 32 * k;
                a0 += wv[k] * tp0[s];
                a1 += wv[k] * tp1[s];
                a2 += wv[k] * tp2[s];
                a3 += wv[k] * tp3[s];
                a4 += wv[k] * tp4[s];
            }
        }
        #pragma unroll
        for (int off = 16; off > 0; off >>= 1) {
            a0 += __shfl_xor_sync(0xFFFFFFFFu, a0, off);
            a1 += __shfl_xor_sync(0xFFFFFFFFu, a1, off);
            a2 += __shfl_xor_sync(0xFFFFFFFFu, a2, off);
            a3 += __shfl_xor_sync(0xFFFFFFFFu, a3, off);
            a4 += __shfl_xor_sync(0xFFFFFFFFu, a4, off);
        }
        if (lane == 0) {
            float* gp = &g_out2[(b * AVAL + a) * NB];
            atomicAdd(gp + 0, a0);
            atomicAdd(gp + 1, a1);
            atomicAdd(gp + 2, a2);
            atomicAdd(gp + 3, a3);
            atomicAdd(gp + 4, a4);
        }
    }

    grid_barrier(&g_bar2);

    // ================= Phase 3: biases + broadcast =======================
    {
        const int gtid = blockIdx.x * TPB + tid;
        for (int f = gtid; f < BVAL * AVAL * AVAL * NB; f += GRID * TPB) {
            const int n = f % NB;
            const int q = f / NB;              // (b*64 + i)*64 + j
            const int i = (q >> 6) & 63;
            const int b = q >> 12;
            out[f] = g_out2[(b * AVAL + i) * NB + n] + b_ll[i] * g_S[n] + b_fl[n];
        }
    }

    // ================= Cleanup: last block resets state ===================
    __shared__ int lastf;
    __threadfence();
    __syncthreads();
    if (tid == 0) lastf = (atomicAdd(&g_fin, 1) == GRID - 1) ? 1 : 0;
    __syncthreads();
    if (lastf) {
        for (int i = tid; i < BVAL * AVAL * NB; i += TPB) g_out2[i] = 0.f;
        __syncthreads();
        if (tid == 0) {
            g_bar1 = 0; g_bar2 = 0; g_fin = 0;
            __threadfence();
        }
    }
}

// ---------------------------------------------------------------------------
extern "C" void kernel_launch(void* const* d_in, const int* in_sizes, int n_in,
                              void* d_out, int out_size) {
    const float* e    = (const float*)d_in[0];
    const float* W_ll = (const float*)d_in[1];
    const float* b_ll = (const float*)d_in[2];
    const float* W_fl = (const float*)d_in[3];
    const float* b_fl = (const float*)d_in[4];
    float* out = (float*)d_out;

    fused_kernel<<<GRID, TPB>>>(e, W_fl, W_ll, b_ll, b_fl, out);
}